// round 1
// baseline (speedup 1.0000x reference)
#include <cuda_runtime.h>

// ---------------- problem constants ----------------
#define BB 8
#define NN 4096
#define CC 512
#define NHH 8
#define HDD 64
#define MAXPP 321
#define EPSF 1e-6f
#define MT (BB*NN)            // 32768 rows
#define BHT (BB*NHH)          // 64 (b,h) pairs
#define NCHUNK 8
#define CHN (NN/NCHUNK)       // 512

// ---------------- scratch (static device globals; no allocs) ----------------
__device__ float d_QS[(size_t)BHT*NN*128];          // q_sim  [bh][n][128] (pos|neg)
__device__ float d_KK[(size_t)BHT*NN*128];          // kk     [bh][n][128]
__device__ float d_V [(size_t)BHT*NN*64];           // v      [bh][n][64]
__device__ float d_G [(size_t)MT*CC];               // gate   [m][c]
__device__ float d_XA[(size_t)MT*CC];               // xa, then (xa+vd)*g in place
__device__ float d_PART[(size_t)BHT*NCHUNK*128*64]; // kv partials
__device__ float d_KSP [(size_t)BHT*NCHUNK*128];    // ksum partials
__device__ float d_KM  [BHT*128];                   // k_mean
__device__ float d_W   [(size_t)BHT*128*64];        // combined [kv1 | perm(kv2)]
__device__ float d_Z   [(size_t)BHT*NN*2];          // z1,z2 per row

// ================= GEMM1: x @ [qg_w; kv_w]^T with fused epilogue =================
// grid (16, 256), 256 thr. col segments: [0,512) q, [512,1024) g, [1024,1536) k, [1536,2048) v
__global__ __launch_bounds__(256) void gemm1_kernel(
    const float* __restrict__ x, const float* __restrict__ qg_w,
    const float* __restrict__ kv_w, const float* __restrict__ scale_p,
    const float* __restrict__ power_p, const float* __restrict__ pos_emb)
{
    __shared__ float As[16][128];
    __shared__ float Bs[16][128];
    __shared__ float sc_s[128], pw_s[128];

    int bx = blockIdx.x, by = blockIdx.y;
    int tid = threadIdx.x;
    int tx = tid & 15, ty = tid >> 4;
    int col0 = bx * 128;
    int m0 = by * 128;
    int seg = bx >> 2;

    const float* Wp = (bx < 8) ? (qg_w + (size_t)col0 * CC)
                               : (kv_w + (size_t)(col0 - 1024) * CC);

    if ((seg == 0 || seg == 2) && tid < 128) {
        int c = (seg == 0) ? (col0 + tid) : (col0 - 1024 + tid);
        sc_s[tid] = log1pf(expf(scale_p[c]));
        pw_s[tid] = 1.0f + 4.0f / (1.0f + expf(-power_p[c]));
    }

    float acc[8][8];
    #pragma unroll
    for (int i = 0; i < 8; i++)
        #pragma unroll
        for (int j = 0; j < 8; j++) acc[i][j] = 0.f;

    int lr = tid >> 2;       // 0..63
    int lc = tid & 3;        // 0..3 (float4 slot)
    for (int kt = 0; kt < CC; kt += 16) {
        #pragma unroll
        for (int rr = 0; rr < 2; rr++) {
            int r = lr + rr * 64;
            float4 v = *(const float4*)(x + (size_t)(m0 + r) * CC + kt + lc * 4);
            As[lc*4+0][r] = v.x; As[lc*4+1][r] = v.y;
            As[lc*4+2][r] = v.z; As[lc*4+3][r] = v.w;
        }
        #pragma unroll
        for (int rr = 0; rr < 2; rr++) {
            int r = lr + rr * 64;
            float4 v = *(const float4*)(Wp + (size_t)r * CC + kt + lc * 4);
            Bs[lc*4+0][r] = v.x; Bs[lc*4+1][r] = v.y;
            Bs[lc*4+2][r] = v.z; Bs[lc*4+3][r] = v.w;
        }
        __syncthreads();
        #pragma unroll
        for (int kk = 0; kk < 16; kk++) {
            float a[8], bq[8];
            #pragma unroll
            for (int i = 0; i < 8; i++) a[i] = As[kk][ty*8+i];
            #pragma unroll
            for (int j = 0; j < 8; j++) bq[j] = Bs[kk][tx*8+j];
            #pragma unroll
            for (int i = 0; i < 8; i++)
                #pragma unroll
                for (int j = 0; j < 8; j++) acc[i][j] += a[i]*bq[j];
        }
        __syncthreads();
    }

    #pragma unroll
    for (int i = 0; i < 8; i++) {
        int m = m0 + ty*8 + i;
        int b = m >> 12, nn2 = m & 4095;
        #pragma unroll
        for (int j = 0; j < 8; j++) {
            int lcl = tx*8 + j;
            float av = acc[i][j];
            if (seg == 0) {                       // q -> q_sim features
                int c = col0 + lcl;
                float qv = av / sc_s[lcl];
                float p  = pw_s[lcl];
                float pos = (qv > 0.f) ? expf(p * logf(qv))  : 0.f;
                float neg = (qv < 0.f) ? expf(p * logf(-qv)) : 0.f;
                int h = c >> 6, d = c & 63;
                size_t base = (((size_t)(b*NHH + h))*NN + nn2) * 128;
                d_QS[base + d]      = pos;
                d_QS[base + 64 + d] = neg;
            } else if (seg == 1) {                // g
                int c = col0 - 512 + lcl;
                d_G[(size_t)m * CC + c] = av;
            } else if (seg == 2) {                // k -> kk features (with pos emb)
                int c = col0 - 1024 + lcl;
                float kvv = (av + pos_emb[(size_t)(nn2 % MAXPP) * CC + c]) / sc_s[lcl];
                float p = pw_s[lcl];
                float pos = (kvv > 0.f) ? expf(p * logf(kvv))  : 0.f;
                float neg = (kvv < 0.f) ? expf(p * logf(-kvv)) : 0.f;
                int h = c >> 6, d = c & 63;
                size_t base = (((size_t)(b*NHH + h))*NN + nn2) * 128;
                d_KK[base + d]      = pos;
                d_KK[base + 64 + d] = neg;
            } else {                              // v
                int c = col0 - 1536 + lcl;
                int h = c >> 6, d = c & 63;
                d_V[(((size_t)(b*NHH + h))*NN + nn2) * 64 + d] = av;
            }
        }
    }
}

// ================= ksum partials: sum_n kk[bh][n][d] over chunk =================
__global__ void ksum_kernel()
{
    int ci = blockIdx.x, bh = blockIdx.y;
    int d = threadIdx.x;
    const float* p = d_KK + ((size_t)bh*NN + (size_t)ci*CHN)*128 + d;
    float s = 0.f;
    #pragma unroll 4
    for (int n = 0; n < CHN; n++) s += p[(size_t)n*128];
    d_KSP[((size_t)bh*NCHUNK + ci)*128 + d] = s;
}

// ================= kv partials: kk_chunk^T @ v_chunk (128x64) =================
__global__ __launch_bounds__(256) void kvpart_kernel()
{
    __shared__ float KKs[16][128];
    __shared__ float Vs[16][64];
    int ci = blockIdx.x, bh = blockIdx.y;
    int tid = threadIdx.x;
    int tx = tid & 15, ty = tid >> 4;
    const float* kkbase = d_KK + ((size_t)bh*NN + (size_t)ci*CHN)*128;
    const float* vbase  = d_V  + ((size_t)bh*NN + (size_t)ci*CHN)*64;

    float acc[8][4];
    #pragma unroll
    for (int i = 0; i < 8; i++)
        #pragma unroll
        for (int j = 0; j < 4; j++) acc[i][j] = 0.f;

    int kr = tid >> 5, kc = tid & 31;   // KK tile loader
    int vr = tid >> 4, vc = tid & 15;   // V tile loader
    for (int nt = 0; nt < CHN; nt += 16) {
        #pragma unroll
        for (int rr = 0; rr < 2; rr++) {
            int r = kr + rr*8;
            float4 v = *(const float4*)(kkbase + (size_t)(nt + r)*128 + kc*4);
            *(float4*)&KKs[r][kc*4] = v;
        }
        {
            float4 v = *(const float4*)(vbase + (size_t)(nt + vr)*64 + vc*4);
            *(float4*)&Vs[vr][vc*4] = v;
        }
        __syncthreads();
        #pragma unroll
        for (int nk = 0; nk < 16; nk++) {
            float a[8], bq[4];
            #pragma unroll
            for (int i = 0; i < 8; i++) a[i] = KKs[nk][ty*8+i];
            #pragma unroll
            for (int j = 0; j < 4; j++) bq[j] = Vs[nk][tx*4+j];
            #pragma unroll
            for (int i = 0; i < 8; i++)
                #pragma unroll
                for (int j = 0; j < 4; j++) acc[i][j] += a[i]*bq[j];
        }
        __syncthreads();
    }
    float* out = d_PART + (((size_t)bh*NCHUNK + ci)*128)*64;
    #pragma unroll
    for (int i = 0; i < 8; i++)
        #pragma unroll
        for (int j = 0; j < 4; j++)
            out[(ty*8+i)*64 + tx*4+j] = acc[i][j];
}

// ================= reduce partials -> k_mean and combined W =================
// W[:, 0:32] = kv1 ; W[d', 32+e'] = kv2[(d'+64)%128][e']  (q_opp folded into W)
__global__ void reduce_kernel()
{
    int bh = blockIdx.x;
    int tid = threadIdx.x;
    const float inv = 1.0f / (float)NN;
    if (tid < 128) {
        float s = 0.f;
        #pragma unroll
        for (int c = 0; c < NCHUNK; c++)
            s += d_KSP[((size_t)bh*NCHUNK + c)*128 + tid];
        d_KM[bh*128 + tid] = s * inv;
    }
    for (int idx = tid; idx < 128*64; idx += 256) {
        int dd = idx >> 6, e = idx & 63;
        float s = 0.f;
        #pragma unroll
        for (int c = 0; c < NCHUNK; c++)
            s += d_PART[(((size_t)bh*NCHUNK + c)*128 + dd)*64 + e];
        s *= inv;
        int dp = (e < 32) ? dd : ((dd + 64) & 127);
        d_W[((size_t)bh*128 + dp)*64 + e] = s;
    }
}

// ================= z1,z2 per row: dots with k_mean / swapped k_mean =================
__global__ __launch_bounds__(256) void z_kernel()
{
    __shared__ float kms[128];
    int bh = blockIdx.y;
    int n0 = blockIdx.x * 128;
    int tid = threadIdx.x;
    if (tid < 128) kms[tid] = d_KM[bh*128 + tid];
    __syncthreads();
    int w = tid >> 5, l = tid & 31;
    for (int it = 0; it < 16; it++) {
        int n = n0 + it*8 + w;
        const float* qp = d_QS + ((size_t)bh*NN + n)*128;
        float q0 = qp[l], q1 = qp[32+l], q2 = qp[64+l], q3 = qp[96+l];
        float s1 = q0*kms[l]    + q1*kms[32+l] + q2*kms[64+l] + q3*kms[96+l];
        float s2 = q0*kms[64+l] + q1*kms[96+l] + q2*kms[l]    + q3*kms[32+l];
        #pragma unroll
        for (int o = 16; o > 0; o >>= 1) {
            s1 += __shfl_down_sync(0xffffffffu, s1, o);
            s2 += __shfl_down_sync(0xffffffffu, s2, o);
        }
        if (l == 0) {
            d_Z[((size_t)bh*NN + n)*2 + 0] = 1.0f / (s1 + EPSF);
            d_Z[((size_t)bh*NN + n)*2 + 1] = 1.0f / (s2 + EPSF);
        }
    }
}

// ================= phase B: X = QS @ W, rows scaled by z1/z2 -> xa =================
__global__ __launch_bounds__(256) void phaseb_kernel()
{
    __shared__ float Ws[128][68];
    __shared__ float QSs[16][128];
    int bh = blockIdx.y;
    int n0 = blockIdx.x * 128;
    int tid = threadIdx.x;
    int tx = tid & 15, ty = tid >> 4;

    const float* wp = d_W + (size_t)bh*128*64;
    for (int idx = tid; idx < 128*16; idx += 256) {
        int r = idx >> 4, c = idx & 15;
        float4 v = *(const float4*)(wp + (size_t)r*64 + c*4);
        *(float4*)&Ws[r][c*4] = v;
    }

    float acc[8][4];
    #pragma unroll
    for (int i = 0; i < 8; i++)
        #pragma unroll
        for (int j = 0; j < 4; j++) acc[i][j] = 0.f;

    int lr = tid >> 2, lc = tid & 3;
    const float* qbase = d_QS + ((size_t)bh*NN + n0)*128;
    for (int kt = 0; kt < 128; kt += 16) {
        #pragma unroll
        for (int rr = 0; rr < 2; rr++) {
            int r = lr + rr*64;
            float4 v = *(const float4*)(qbase + (size_t)r*128 + kt + lc*4);
            QSs[lc*4+0][r] = v.x; QSs[lc*4+1][r] = v.y;
            QSs[lc*4+2][r] = v.z; QSs[lc*4+3][r] = v.w;
        }
        __syncthreads();
        #pragma unroll
        for (int kk = 0; kk < 16; kk++) {
            float a[8], bq[4];
            #pragma unroll
            for (int i = 0; i < 8; i++) a[i] = QSs[kk][ty*8+i];
            #pragma unroll
            for (int j = 0; j < 4; j++) bq[j] = Ws[kt+kk][tx*4+j];
            #pragma unroll
            for (int i = 0; i < 8; i++)
                #pragma unroll
                for (int j = 0; j < 4; j++) acc[i][j] += a[i]*bq[j];
        }
        __syncthreads();
    }

    int b = bh >> 3, h = bh & 7;
    #pragma unroll
    for (int i = 0; i < 8; i++) {
        int n = n0 + ty*8 + i;
        const float* zp = d_Z + ((size_t)bh*NN + n)*2;
        float zz = (tx < 8) ? zp[0] : zp[1];
        #pragma unroll
        for (int j = 0; j < 4; j++) {
            int lcl = tx*4 + j;
            d_XA[((size_t)b*NN + n)*CC + h*64 + lcl] = acc[i][j] * zz;
        }
    }
}

// ================= depthwise 5x5 conv fused with (xa+vd+bias)*g =================
// v buffer per batch reinterpreted as [64 c'][4096 m][8 w]; output index:
// ch = c'*8 + m/512, n' = (m%512)*8 + w.  Updates d_XA in place.
__global__ __launch_bounds__(256) void conv_kernel(const float* __restrict__ dwc_w,
                                                   const float* __restrict__ dwc_b)
{
    __shared__ float sm[64][145];   // [cg][12m x 12w], +1 pad => conflict-free
    int t_ch = blockIdx.x;          // 0..7 (8 c' per block)
    int t_n  = blockIdx.y;          // 0..63 (64 n' per block)
    int b    = blockIdx.z;
    int tid = threadIdx.x;
    int n0 = t_n * 64;
    int mmbase = t_n * 8;

    float* smf = &sm[0][0];
    for (int idx = tid; idx < 64*145; idx += 256) smf[idx] = 0.f;
    __syncthreads();

    const float* vb = d_V + (size_t)b * ((size_t)NHH*NN*HDD);
    for (int idx = tid; idx < 64*96; idx += 256) {
        int cg = idx / 96;
        int rem = idx - cg*96;
        int mr = rem >> 3, w = rem & 7;
        int cp = t_ch*8 + (cg >> 3);
        int g  = cg & 7;
        int m  = g*512 + mmbase - 2 + mr;
        float v = 0.f;
        if (m >= 0 && m < NN) v = vb[(size_t)cp*32768 + (size_t)m*8 + w];
        sm[cg][mr*12 + w + 2] = v;
    }
    __syncthreads();

    int ch_l = tid & 63;
    int cp = t_ch*8 + (ch_l >> 3);
    float wgt[25];
    #pragma unroll
    for (int i = 0; i < 25; i++) wgt[i] = dwc_w[cp*25 + i];
    float bias = dwc_b[cp];
    int chg = t_ch*64 + ch_l;
    #pragma unroll
    for (int r = 0; r < 16; r++) {
        int nl = (tid >> 6) + (r << 2);
        int mm = nl >> 3, w = nl & 7;
        float o = 0.f;
        #pragma unroll
        for (int i = 0; i < 5; i++)
            #pragma unroll
            for (int j = 0; j < 5; j++)
                o += wgt[i*5+j] * sm[ch_l][(mm+i)*12 + w + j];
        size_t oi = ((size_t)b*NN + (n0 + nl)) * CC + chg;
        d_XA[oi] = (d_XA[oi] + o + bias) * d_G[oi];
    }
}

// ================= proj: out = A @ proj_w^T + proj_b =================
__global__ __launch_bounds__(256) void proj_kernel(const float* __restrict__ pw,
                                                   const float* __restrict__ pb,
                                                   float* __restrict__ out)
{
    __shared__ float As[16][128];
    __shared__ float Bs[16][128];
    int bx = blockIdx.x, by = blockIdx.y;
    int tid = threadIdx.x;
    int tx = tid & 15, ty = tid >> 4;
    int col0 = bx * 128;
    int m0 = by * 128;

    float acc[8][8];
    #pragma unroll
    for (int i = 0; i < 8; i++)
        #pragma unroll
        for (int j = 0; j < 8; j++) acc[i][j] = 0.f;

    int lr = tid >> 2, lc = tid & 3;
    for (int kt = 0; kt < CC; kt += 16) {
        #pragma unroll
        for (int rr = 0; rr < 2; rr++) {
            int r = lr + rr*64;
            float4 v = *(const float4*)(d_XA + (size_t)(m0 + r) * CC + kt + lc * 4);
            As[lc*4+0][r] = v.x; As[lc*4+1][r] = v.y;
            As[lc*4+2][r] = v.z; As[lc*4+3][r] = v.w;
        }
        #pragma unroll
        for (int rr = 0; rr < 2; rr++) {
            int r = lr + rr*64;
            float4 v = *(const float4*)(pw + (size_t)(col0 + r) * CC + kt + lc * 4);
            Bs[lc*4+0][r] = v.x; Bs[lc*4+1][r] = v.y;
            Bs[lc*4+2][r] = v.z; Bs[lc*4+3][r] = v.w;
        }
        __syncthreads();
        #pragma unroll
        for (int kk = 0; kk < 16; kk++) {
            float a[8], bq[8];
            #pragma unroll
            for (int i = 0; i < 8; i++) a[i] = As[kk][ty*8+i];
            #pragma unroll
            for (int j = 0; j < 8; j++) bq[j] = Bs[kk][tx*8+j];
            #pragma unroll
            for (int i = 0; i < 8; i++)
                #pragma unroll
                for (int j = 0; j < 8; j++) acc[i][j] += a[i]*bq[j];
        }
        __syncthreads();
    }

    #pragma unroll
    for (int i = 0; i < 8; i++) {
        int m = m0 + ty*8 + i;
        #pragma unroll
        for (int j = 0; j < 8; j++) {
            int c = col0 + tx*8 + j;
            out[(size_t)m * CC + c] = acc[i][j] + pb[c];
        }
    }
}

// ================= launch =================
extern "C" void kernel_launch(void* const* d_in, const int* in_sizes, int n_in,
                              void* d_out, int out_size)
{
    const float* x       = (const float*)d_in[0];
    const float* qg_w    = (const float*)d_in[1];
    const float* kv_w    = (const float*)d_in[2];
    const float* proj_w  = (const float*)d_in[3];
    const float* proj_b  = (const float*)d_in[4];
    const float* power_p = (const float*)d_in[5];
    const float* scale_p = (const float*)d_in[6];
    const float* pos_emb = (const float*)d_in[7];
    const float* dwc_w   = (const float*)d_in[8];
    const float* dwc_b   = (const float*)d_in[9];
    float* out = (float*)d_out;

    gemm1_kernel<<<dim3(16, 256), 256>>>(x, qg_w, kv_w, scale_p, power_p, pos_emb);
    ksum_kernel<<<dim3(NCHUNK, BHT), 128>>>();
    kvpart_kernel<<<dim3(NCHUNK, BHT), 256>>>();
    reduce_kernel<<<BHT, 256>>>();
    z_kernel<<<dim3(32, BHT), 256>>>();
    phaseb_kernel<<<dim3(32, BHT), 256>>>();
    conv_kernel<<<dim3(8, 64, BB), 256>>>(dwc_w, dwc_b);
    proj_kernel<<<dim3(4, 256), 256>>>(proj_w, proj_b, out);
}

// round 3
// speedup vs baseline: 1.7363x; 1.7363x over previous
#include <cuda_runtime.h>
#include <cuda_bf16.h>
#include <cstdint>

// ---------------- problem constants ----------------
#define BB 8
#define NN 4096
#define CC 512
#define NHH 8
#define HDD 64
#define MAXPP 321
#define EPSF 1e-6f
#define MT (BB*NN)            // 32768 rows
#define BHT (BB*NHH)          // 64 (b,h) pairs
#define NCHUNK 8
#define CHN (NN/NCHUNK)       // 512

// ---------------- scratch (static device globals; no allocs) ----------------
__device__ float d_QS[(size_t)BHT*NN*128];          // q_sim  [bh][n][128] (pos|neg)
__device__ float d_KK[(size_t)BHT*NN*128];          // kk     [bh][n][128]
__device__ float d_V [(size_t)BHT*NN*64];           // v      [bh][n][64]
__device__ float d_G [(size_t)MT*CC];               // gate   [m][c]
__device__ float d_XA[(size_t)MT*CC];               // xa, then (xa+vd)*g in place
__device__ float d_PART[(size_t)BHT*NCHUNK*128*64]; // kv partials
__device__ float d_KSP [(size_t)BHT*NCHUNK*128];    // ksum partials
__device__ float d_KM  [BHT*128];                   // k_mean
__device__ float d_W   [(size_t)BHT*128*64];        // combined [kv1 | perm(kv2)]
__device__ float d_Z   [(size_t)BHT*NN*2];          // z1,z2 per row

// ---------------- mma helpers (portable sm_80+ path; NO tcgen05) ----------------
__device__ __forceinline__ uint32_t smem_u32(const void* p) {
    uint32_t r;
    asm("{ .reg .u64 t; cvta.to.shared.u64 t, %1; cvt.u32.u64 %0, t; }" : "=r"(r) : "l"(p));
    return r;
}
__device__ __forceinline__ void ldsm4(uint32_t* r, uint32_t addr) {
    asm volatile("ldmatrix.sync.aligned.m8n8.x4.shared.b16 {%0,%1,%2,%3}, [%4];"
                 : "=r"(r[0]), "=r"(r[1]), "=r"(r[2]), "=r"(r[3]) : "r"(addr));
}
__device__ __forceinline__ void mma_bf16(float* c, const uint32_t* a, uint32_t b0, uint32_t b1) {
    asm volatile("mma.sync.aligned.m16n8k16.row.col.f32.bf16.bf16.f32 "
                 "{%0,%1,%2,%3}, {%4,%5,%6,%7}, {%8,%9}, {%0,%1,%2,%3};"
                 : "+f"(c[0]), "+f"(c[1]), "+f"(c[2]), "+f"(c[3])
                 : "r"(a[0]), "r"(a[1]), "r"(a[2]), "r"(a[3]), "r"(b0), "r"(b1));
}

// SMEM tile: 128 rows x 32 k-elems, padded to 40 elems/row (80B stride ->
// conflict-free ldmatrix: r*80 mod 128 distinct over 8 rows).
#define TPAD 40
#define TROWB (TPAD*2)        // 80 bytes per row
#define MTILEB (16*TROWB)     // 1280 bytes per 16-row tile

// ================= unified bf16x3 tensor-core GEMM =================
// MODE 0: gemm1  (A = x [m0 tile], B = [qg_w;kv_w], fused feature-map epilogue)
// MODE 1: proj   (A = d_XA, B = proj_w, +bias -> out)
template<int MODE>
__global__ __launch_bounds__(256) void gemm_mma(
    const float* __restrict__ Ain, const float* __restrict__ qg_w,
    const float* __restrict__ kv_w, const float* __restrict__ scale_p,
    const float* __restrict__ power_p, const float* __restrict__ pos_emb,
    const float* __restrict__ pb, float* __restrict__ outp)
{
    __shared__ __nv_bfloat16 sAhi[128*TPAD], sAlo[128*TPAD];
    __shared__ __nv_bfloat16 sBhi[128*TPAD], sBlo[128*TPAD];
    __shared__ float inv_sc[128], pw_s[128];

    int tid = threadIdx.x;
    int wid = tid >> 5;
    int lane = tid & 31;
    int bx = blockIdx.x, by = blockIdx.y;
    int col0 = bx * 128;
    int m0 = by * 128;
    int seg = (MODE == 0) ? (bx >> 2) : 0;

    if (MODE == 0 && (seg == 0 || seg == 2) && tid < 128) {
        int c = (seg == 0) ? (col0 + tid) : (col0 - 1024 + tid);
        inv_sc[tid] = 1.0f / log1pf(expf(scale_p[c]));
        pw_s[tid]   = 1.0f + 4.0f / (1.0f + expf(-power_p[c]));
    }

    const float* Aptr = (MODE == 0) ? Ain : d_XA;
    const float* Bptr;
    if (MODE == 0) Bptr = (bx < 8) ? (qg_w + (size_t)col0 * CC)
                                   : (kv_w + (size_t)(col0 - 1024) * CC);
    else           Bptr = qg_w /*proj_w*/ + (size_t)col0 * CC;

    // warp tiling: 4 warps over M (32 rows each), 2 warps over N (64 cols each)
    int wm = (wid & 3) * 32;
    int wn = (wid >> 2) * 64;

    // ldmatrix per-lane byte offsets
    uint32_t aoff = (uint32_t)((wm + (lane & 15)) * TROWB + ((lane >> 4) * 8) * 2);
    uint32_t boff = (uint32_t)((wn + (lane & 7) + ((lane >> 4) & 1) * 8) * TROWB
                               + (((lane >> 3) & 1) * 8) * 2);
    uint32_t aAhi = smem_u32(sAhi) + aoff;
    uint32_t aAlo = smem_u32(sAlo) + aoff;
    uint32_t aBhi = smem_u32(sBhi) + boff;
    uint32_t aBlo = smem_u32(sBlo) + boff;

    // loader mapping: thread -> (row, k-half)
    int lrow = tid >> 1;
    int lkh  = (tid & 1) * 16;

    float acc[2][8][4];
    #pragma unroll
    for (int mt = 0; mt < 2; mt++)
        #pragma unroll
        for (int j = 0; j < 8; j++)
            #pragma unroll
            for (int e = 0; e < 4; e++) acc[mt][j][e] = 0.f;

    #pragma unroll 1
    for (int kc = 0; kc < 16; kc++) {
        // ---- load fp32 chunk, split into bf16 hi/lo ----
        {
            const float4* ga = (const float4*)(Aptr + (size_t)(m0 + lrow) * CC + kc * 32 + lkh);
            const float4* gb = (const float4*)(Bptr + (size_t)lrow * CC + kc * 32 + lkh);
            float4 va[4], vb[4];
            #pragma unroll
            for (int i = 0; i < 4; i++) va[i] = ga[i];
            #pragma unroll
            for (int i = 0; i < 4; i++) vb[i] = gb[i];

            __nv_bfloat162* pAh = (__nv_bfloat162*)(sAhi + lrow * TPAD + lkh);
            __nv_bfloat162* pAl = (__nv_bfloat162*)(sAlo + lrow * TPAD + lkh);
            __nv_bfloat162* pBh = (__nv_bfloat162*)(sBhi + lrow * TPAD + lkh);
            __nv_bfloat162* pBl = (__nv_bfloat162*)(sBlo + lrow * TPAD + lkh);
            #pragma unroll
            for (int i = 0; i < 4; i++) {
                float xs[4] = {va[i].x, va[i].y, va[i].z, va[i].w};
                __nv_bfloat16 h0 = __float2bfloat16_rn(xs[0]);
                __nv_bfloat16 h1 = __float2bfloat16_rn(xs[1]);
                __nv_bfloat16 h2 = __float2bfloat16_rn(xs[2]);
                __nv_bfloat16 h3 = __float2bfloat16_rn(xs[3]);
                pAh[2*i]   = __halves2bfloat162(h0, h1);
                pAh[2*i+1] = __halves2bfloat162(h2, h3);
                pAl[2*i]   = __halves2bfloat162(__float2bfloat16_rn(xs[0] - __bfloat162float(h0)),
                                                __float2bfloat16_rn(xs[1] - __bfloat162float(h1)));
                pAl[2*i+1] = __halves2bfloat162(__float2bfloat16_rn(xs[2] - __bfloat162float(h2)),
                                                __float2bfloat16_rn(xs[3] - __bfloat162float(h3)));
            }
            #pragma unroll
            for (int i = 0; i < 4; i++) {
                float xs[4] = {vb[i].x, vb[i].y, vb[i].z, vb[i].w};
                __nv_bfloat16 h0 = __float2bfloat16_rn(xs[0]);
                __nv_bfloat16 h1 = __float2bfloat16_rn(xs[1]);
                __nv_bfloat16 h2 = __float2bfloat16_rn(xs[2]);
                __nv_bfloat16 h3 = __float2bfloat16_rn(xs[3]);
                pBh[2*i]   = __halves2bfloat162(h0, h1);
                pBh[2*i+1] = __halves2bfloat162(h2, h3);
                pBl[2*i]   = __halves2bfloat162(__float2bfloat16_rn(xs[0] - __bfloat162float(h0)),
                                                __float2bfloat16_rn(xs[1] - __bfloat162float(h1)));
                pBl[2*i+1] = __halves2bfloat162(__float2bfloat16_rn(xs[2] - __bfloat162float(h2)),
                                                __float2bfloat16_rn(xs[3] - __bfloat162float(h3)));
            }
        }
        __syncthreads();

        // ---- MMA: 3 terms (hh, hl, lh) over 2 k16 sub-chunks ----
        #pragma unroll
        for (int s = 0; s < 2; s++) {
            uint32_t ah[2][4], al[2][4];
            ldsm4(ah[0], aAhi + s*32);
            ldsm4(ah[1], aAhi + MTILEB + s*32);
            ldsm4(al[0], aAlo + s*32);
            ldsm4(al[1], aAlo + MTILEB + s*32);
            #pragma unroll
            for (int p = 0; p < 4; p++) {
                uint32_t bh[4], bl[4];
                ldsm4(bh, aBhi + p*MTILEB + s*32);
                ldsm4(bl, aBlo + p*MTILEB + s*32);
                #pragma unroll
                for (int mt = 0; mt < 2; mt++) {
                    #pragma unroll
                    for (int h2 = 0; h2 < 2; h2++) {
                        float* c = acc[mt][p*2 + h2];
                        mma_bf16(c, ah[mt], bh[2*h2], bh[2*h2+1]);
                        mma_bf16(c, ah[mt], bl[2*h2], bl[2*h2+1]);
                        mma_bf16(c, al[mt], bh[2*h2], bh[2*h2+1]);
                    }
                }
            }
        }
        __syncthreads();
    }

    // ---- epilogue ----
    int g = lane >> 2, tg = lane & 3;
    #pragma unroll
    for (int mt = 0; mt < 2; mt++) {
        #pragma unroll
        for (int j = 0; j < 8; j++) {
            int cl0 = wn + j*8 + 2*tg;
            #pragma unroll
            for (int half = 0; half < 2; half++) {    // rows g, g+8
                int r = wm + mt*16 + g + half*8;
                int m = m0 + r;
                float a0 = acc[mt][j][half*2 + 0];
                float a1 = acc[mt][j][half*2 + 1];
                if (MODE == 1) {
                    int cg = col0 + cl0;
                    float2 o = make_float2(a0 + pb[cg], a1 + pb[cg+1]);
                    *(float2*)(outp + (size_t)m * CC + cg) = o;
                } else {
                    int b = m >> 12, n = m & 4095;
                    #pragma unroll
                    for (int e = 0; e < 2; e++) {
                        int cl = cl0 + e;
                        float av = (e == 0) ? a0 : a1;
                        if (seg == 0) {
                            int cg = col0 + cl;
                            float qv = av * inv_sc[cl];
                            float p = pw_s[cl];
                            float pos = (qv > 0.f) ? expf(p * logf(qv))  : 0.f;
                            float neg = (qv < 0.f) ? expf(p * logf(-qv)) : 0.f;
                            int h = cg >> 6, d = cg & 63;
                            size_t base = (((size_t)(b*NHH + h))*NN + n) * 128;
                            d_QS[base + d]      = pos;
                            d_QS[base + 64 + d] = neg;
                        } else if (seg == 1) {
                            int cg = col0 - 512 + cl;
                            d_G[(size_t)m * CC + cg] = av;
                        } else if (seg == 2) {
                            int cg = col0 - 1024 + cl;
                            float kvv = (av + pos_emb[(size_t)(n % MAXPP) * CC + cg]) * inv_sc[cl];
                            float p = pw_s[cl];
                            float pos = (kvv > 0.f) ? expf(p * logf(kvv))  : 0.f;
                            float neg = (kvv < 0.f) ? expf(p * logf(-kvv)) : 0.f;
                            int h = cg >> 6, d = cg & 63;
                            size_t base = (((size_t)(b*NHH + h))*NN + n) * 128;
                            d_KK[base + d]      = pos;
                            d_KK[base + 64 + d] = neg;
                        } else {
                            int cg = col0 - 1536 + cl;
                            int h = cg >> 6, d = cg & 63;
                            d_V[(((size_t)(b*NHH + h))*NN + n) * 64 + d] = av;
                        }
                    }
                }
            }
        }
    }
}

// ================= ksum partials: sum_n kk[bh][n][d] over chunk =================
__global__ void ksum_kernel()
{
    int ci = blockIdx.x, bh = blockIdx.y;
    int d = threadIdx.x;
    const float* p = d_KK + ((size_t)bh*NN + (size_t)ci*CHN)*128 + d;
    float s = 0.f;
    #pragma unroll 4
    for (int n = 0; n < CHN; n++) s += p[(size_t)n*128];
    d_KSP[((size_t)bh*NCHUNK + ci)*128 + d] = s;
}

// ================= kv partials: kk_chunk^T @ v_chunk (128x64) =================
__global__ __launch_bounds__(256) void kvpart_kernel()
{
    __shared__ float KKs[16][128];
    __shared__ float Vs[16][64];
    int ci = blockIdx.x, bh = blockIdx.y;
    int tid = threadIdx.x;
    int tx = tid & 15, ty = tid >> 4;
    const float* kkbase = d_KK + ((size_t)bh*NN + (size_t)ci*CHN)*128;
    const float* vbase  = d_V  + ((size_t)bh*NN + (size_t)ci*CHN)*64;

    float acc[8][4];
    #pragma unroll
    for (int i = 0; i < 8; i++)
        #pragma unroll
        for (int j = 0; j < 4; j++) acc[i][j] = 0.f;

    int kr = tid >> 5, kc = tid & 31;
    int vr = tid >> 4, vc = tid & 15;
    for (int nt = 0; nt < CHN; nt += 16) {
        #pragma unroll
        for (int rr = 0; rr < 2; rr++) {
            int r = kr + rr*8;
            float4 v = *(const float4*)(kkbase + (size_t)(nt + r)*128 + kc*4);
            *(float4*)&KKs[r][kc*4] = v;
        }
        {
            float4 v = *(const float4*)(vbase + (size_t)(nt + vr)*64 + vc*4);
            *(float4*)&Vs[vr][vc*4] = v;
        }
        __syncthreads();
        #pragma unroll
        for (int nk = 0; nk < 16; nk++) {
            float a[8], bq[4];
            #pragma unroll
            for (int i = 0; i < 8; i++) a[i] = KKs[nk][ty*8+i];
            #pragma unroll
            for (int j = 0; j < 4; j++) bq[j] = Vs[nk][tx*4+j];
            #pragma unroll
            for (int i = 0; i < 8; i++)
                #pragma unroll
                for (int j = 0; j < 4; j++) acc[i][j] += a[i]*bq[j];
        }
        __syncthreads();
    }
    float* out = d_PART + (((size_t)bh*NCHUNK + ci)*128)*64;
    #pragma unroll
    for (int i = 0; i < 8; i++)
        #pragma unroll
        for (int j = 0; j < 4; j++)
            out[(ty*8+i)*64 + tx*4+j] = acc[i][j];
}

// ================= reduce partials -> k_mean and combined W =================
__global__ void reduce_kernel()
{
    int bh = blockIdx.x;
    int tid = threadIdx.x;
    const float inv = 1.0f / (float)NN;
    if (tid < 128) {
        float s = 0.f;
        #pragma unroll
        for (int c = 0; c < NCHUNK; c++)
            s += d_KSP[((size_t)bh*NCHUNK + c)*128 + tid];
        d_KM[bh*128 + tid] = s * inv;
    }
    for (int idx = tid; idx < 128*64; idx += 256) {
        int dd = idx >> 6, e = idx & 63;
        float s = 0.f;
        #pragma unroll
        for (int c = 0; c < NCHUNK; c++)
            s += d_PART[(((size_t)bh*NCHUNK + c)*128 + dd)*64 + e];
        s *= inv;
        int dp = (e < 32) ? dd : ((dd + 64) & 127);
        d_W[((size_t)bh*128 + dp)*64 + e] = s;
    }
}

// ================= z1,z2 per row =================
__global__ __launch_bounds__(256) void z_kernel()
{
    __shared__ float kms[128];
    int bh = blockIdx.y;
    int n0 = blockIdx.x * 128;
    int tid = threadIdx.x;
    if (tid < 128) kms[tid] = d_KM[bh*128 + tid];
    __syncthreads();
    int w = tid >> 5, l = tid & 31;
    for (int it = 0; it < 16; it++) {
        int n = n0 + it*8 + w;
        const float* qp = d_QS + ((size_t)bh*NN + n)*128;
        float q0 = qp[l], q1 = qp[32+l], q2 = qp[64+l], q3 = qp[96+l];
        float s1 = q0*kms[l]    + q1*kms[32+l] + q2*kms[64+l] + q3*kms[96+l];
        float s2 = q0*kms[64+l] + q1*kms[96+l] + q2*kms[l]    + q3*kms[32+l];
        #pragma unroll
        for (int o = 16; o > 0; o >>= 1) {
            s1 += __shfl_down_sync(0xffffffffu, s1, o);
            s2 += __shfl_down_sync(0xffffffffu, s2, o);
        }
        if (l == 0) {
            d_Z[((size_t)bh*NN + n)*2 + 0] = 1.0f / (s1 + EPSF);
            d_Z[((size_t)bh*NN + n)*2 + 1] = 1.0f / (s2 + EPSF);
        }
    }
}

// ================= phase B: X = QS @ W, rows scaled by z1/z2 -> xa =================
__global__ __launch_bounds__(256) void phaseb_kernel()
{
    __shared__ float Ws[128][68];
    __shared__ float QSs[16][128];
    int bh = blockIdx.y;
    int n0 = blockIdx.x * 128;
    int tid = threadIdx.x;
    int tx = tid & 15, ty = tid >> 4;

    const float* wp = d_W + (size_t)bh*128*64;
    for (int idx = tid; idx < 128*16; idx += 256) {
        int r = idx >> 4, c = idx & 15;
        float4 v = *(const float4*)(wp + (size_t)r*64 + c*4);
        *(float4*)&Ws[r][c*4] = v;
    }

    float acc[8][4];
    #pragma unroll
    for (int i = 0; i < 8; i++)
        #pragma unroll
        for (int j = 0; j < 4; j++) acc[i][j] = 0.f;

    int lr = tid >> 2, lc = tid & 3;
    const float* qbase = d_QS + ((size_t)bh*NN + n0)*128;
    for (int kt = 0; kt < 128; kt += 16) {
        #pragma unroll
        for (int rr = 0; rr < 2; rr++) {
            int r = lr + rr*64;
            float4 v = *(const float4*)(qbase + (size_t)r*128 + kt + lc*4);
            QSs[lc*4+0][r] = v.x; QSs[lc*4+1][r] = v.y;
            QSs[lc*4+2][r] = v.z; QSs[lc*4+3][r] = v.w;
        }
        __syncthreads();
        #pragma unroll
        for (int kk = 0; kk < 16; kk++) {
            float a[8], bq[4];
            #pragma unroll
            for (int i = 0; i < 8; i++) a[i] = QSs[kk][ty*8+i];
            #pragma unroll
            for (int j = 0; j < 4; j++) bq[j] = Ws[kt+kk][tx*4+j];
            #pragma unroll
            for (int i = 0; i < 8; i++)
                #pragma unroll
                for (int j = 0; j < 4; j++) acc[i][j] += a[i]*bq[j];
        }
        __syncthreads();
    }

    int b = bh >> 3, h = bh & 7;
    #pragma unroll
    for (int i = 0; i < 8; i++) {
        int n = n0 + ty*8 + i;
        const float* zp = d_Z + ((size_t)bh*NN + n)*2;
        float zz = (tx < 8) ? zp[0] : zp[1];
        #pragma unroll
        for (int j = 0; j < 4; j++) {
            int lcl = tx*4 + j;
            d_XA[((size_t)b*NN + n)*CC + h*64 + lcl] = acc[i][j] * zz;
        }
    }
}

// ================= depthwise 5x5 conv fused with (xa+vd+bias)*g =================
__global__ __launch_bounds__(256) void conv_kernel(const float* __restrict__ dwc_w,
                                                   const float* __restrict__ dwc_b)
{
    __shared__ float sm[64][145];
    int t_ch = blockIdx.x;
    int t_n  = blockIdx.y;
    int b    = blockIdx.z;
    int tid = threadIdx.x;
    int n0 = t_n * 64;
    int mmbase = t_n * 8;

    float* smf = &sm[0][0];
    for (int idx = tid; idx < 64*145; idx += 256) smf[idx] = 0.f;
    __syncthreads();

    const float* vb = d_V + (size_t)b * ((size_t)NHH*NN*HDD);
    for (int idx = tid; idx < 64*96; idx += 256) {
        int cg = idx / 96;
        int rem = idx - cg*96;
        int mr = rem >> 3, w = rem & 7;
        int cp = t_ch*8 + (cg >> 3);
        int g  = cg & 7;
        int m  = g*512 + mmbase - 2 + mr;
        float v = 0.f;
        if (m >= 0 && m < NN) v = vb[(size_t)cp*32768 + (size_t)m*8 + w];
        sm[cg][mr*12 + w + 2] = v;
    }
    __syncthreads();

    int ch_l = tid & 63;
    int cp = t_ch*8 + (ch_l >> 3);
    float wgt[25];
    #pragma unroll
    for (int i = 0; i < 25; i++) wgt[i] = dwc_w[cp*25 + i];
    float bias = dwc_b[cp];
    int chg = t_ch*64 + ch_l;
    #pragma unroll
    for (int r = 0; r < 16; r++) {
        int nl = (tid >> 6) + (r << 2);
        int mm = nl >> 3, w = nl & 7;
        float o = 0.f;
        #pragma unroll
        for (int i = 0; i < 5; i++)
            #pragma unroll
            for (int j = 0; j < 5; j++)
                o += wgt[i*5+j] * sm[ch_l][(mm+i)*12 + w + j];
        size_t oi = ((size_t)b*NN + (n0 + nl)) * CC + chg;
        d_XA[oi] = (d_XA[oi] + o + bias) * d_G[oi];
    }
}

// ================= launch =================
extern "C" void kernel_launch(void* const* d_in, const int* in_sizes, int n_in,
                              void* d_out, int out_size)
{
    const float* x       = (const float*)d_in[0];
    const float* qg_w    = (const float*)d_in[1];
    const float* kv_w    = (const float*)d_in[2];
    const float* proj_w  = (const float*)d_in[3];
    const float* proj_b  = (const float*)d_in[4];
    const float* power_p = (const float*)d_in[5];
    const float* scale_p = (const float*)d_in[6];
    const float* pos_emb = (const float*)d_in[7];
    const float* dwc_w   = (const float*)d_in[8];
    const float* dwc_b   = (const float*)d_in[9];
    float* out = (float*)d_out;

    gemm_mma<0><<<dim3(16, 256), 256>>>(x, qg_w, kv_w, scale_p, power_p,
                                        pos_emb, proj_b, out);
    ksum_kernel<<<dim3(NCHUNK, BHT), 128>>>();
    kvpart_kernel<<<dim3(NCHUNK, BHT), 256>>>();
    reduce_kernel<<<BHT, 256>>>();
    z_kernel<<<dim3(32, BHT), 256>>>();
    phaseb_kernel<<<dim3(32, BHT), 256>>>();
    conv_kernel<<<dim3(8, 64, BB), 256>>>(dwc_w, dwc_b);
    gemm_mma<1><<<dim3(4, 256), 256>>>(nullptr, proj_w, nullptr, nullptr, nullptr,
                                       nullptr, proj_b, out);
}